// round 3
// baseline (speedup 1.0000x reference)
#include <cuda_runtime.h>
#include <math.h>

#define RULES 512
#define FEAT  128
#define RES   5
#define BATCH 2048
#define THREADS 128

// Precomputed per-rule constants (written by prep kernel; no allocations).
__device__ double g_K0[RULES];        // r[i] - e^d * 128 * a[i]^2
__device__ double g_K1[RULES];        // 2 * e^d * a[i]
__device__ float  g_beliefs[RULES * RES];  // softmax(b, axis=-1)
__device__ double g_ed;               // e^d

__global__ void prep_kernel(const float* __restrict__ a,
                            const float* __restrict__ bmat,
                            const float* __restrict__ r,
                            const float* __restrict__ d) {
    int i = blockIdx.x * blockDim.x + threadIdx.x;
    float ed = expf(d[0]);
    if (i < RULES) {
        double av  = (double)a[i];
        double edd = (double)ed;
        g_K1[i] = 2.0 * edd * av;
        g_K0[i] = (double)r[i] - edd * 128.0 * av * av;
        // softmax over the 5 consequent grades (fp32, max-subtracted like jax)
        float bv[RES];
        float m = -1e30f;
        #pragma unroll
        for (int j = 0; j < RES; j++) { bv[j] = bmat[i * RES + j]; m = fmaxf(m, bv[j]); }
        float sum = 0.f;
        #pragma unroll
        for (int j = 0; j < RES; j++) { bv[j] = expf(bv[j] - m); sum += bv[j]; }
        float inv = 1.0f / sum;
        #pragma unroll
        for (int j = 0; j < RES; j++) g_beliefs[i * RES + j] = bv[j] * inv;
    }
    if (i == 0) g_ed = (double)ed;
}

__device__ __forceinline__ float warpSumF(float v) {
    #pragma unroll
    for (int o = 16; o; o >>= 1) v += __shfl_xor_sync(0xffffffffu, v, o);
    return v;
}
__device__ __forceinline__ double warpSumD(double v) {
    #pragma unroll
    for (int o = 16; o; o >>= 1) v += __shfl_xor_sync(0xffffffffu, v, o);
    return v;
}
__device__ __forceinline__ float warpProdF(float v) {
    #pragma unroll
    for (int o = 16; o; o >>= 1) v *= __shfl_xor_sync(0xffffffffu, v, o);
    return v;
}

__global__ void __launch_bounds__(THREADS)
main_kernel(const float* __restrict__ x, float* __restrict__ out) {
    __shared__ float  s_aw[RULES];
    __shared__ float  s_red[8];      // 4 warps x {Sx, Sxx}
    __shared__ double s_dred[4];
    __shared__ float  s_pred[4 * RES];
    __shared__ float  s_bcast[2];
    __shared__ double s_sb;

    const int b = blockIdx.x;
    const int t = threadIdx.x;
    const int w = t >> 5;
    const int l = t & 31;

    // ---- Sx, Sxx over the 128 features (x scaled by 1/5) ----
    float xv = x[b * FEAT + t] * 0.2f;
    float sx  = warpSumF(xv);
    float sxx = warpSumF(xv * xv);
    if (l == 0) { s_red[w] = sx; s_red[4 + w] = sxx; }
    __syncthreads();
    if (t == 0) {
        float A = 0.f, C = 0.f;
        #pragma unroll
        for (int i = 0; i < 4; i++) { A += s_red[i]; C += s_red[4 + i]; }
        s_bcast[0] = A; s_bcast[1] = C;
    }
    __syncthreads();
    const double Sx  = (double)s_bcast[0];
    const double Sxx = (double)s_bcast[1];
    const double ed  = g_ed;
    const double edSxx = ed * Sxx;

    // ---- rule activations (fp64 exponent combine, fp32 exp) ----
    double spart = 0.0;
    #pragma unroll
    for (int i = 0; i < 4; i++) {
        int rr = t + i * THREADS;
        double la = fma(g_K1[rr], Sx, g_K0[rr]) - edSxx;
        float aw = expf((float)la);
        s_aw[rr] = aw;
        spart += (double)aw;
    }
    spart = warpSumD(spart);
    if (l == 0) s_dred[w] = spart;
    __syncthreads();
    if (t == 0) {
        double s = 0.0;
        #pragma unroll
        for (int i = 0; i < 4; i++) s += s_dred[i];
        s_sb = s;
    }
    __syncthreads();
    const double s = s_sb;

    // ---- evidential-reasoning combine: product over rules ----
    float p0 = 1.f, p1 = 1.f, p2 = 1.f, p3 = 1.f, p4 = 1.f;
    #pragma unroll
    for (int i = 0; i < 4; i++) {
        int rr = t + i * THREADS;
        float aw = s_aw[rr];
        float den = (float)(s - (double)aw);   // fp64 subtraction: no cancellation blow-up
        float ratio = aw / den;
        const float* bl = &g_beliefs[rr * RES];
        p0 *= fmaf(ratio, bl[0], 1.0f);
        p1 *= fmaf(ratio, bl[1], 1.0f);
        p2 *= fmaf(ratio, bl[2], 1.0f);
        p3 *= fmaf(ratio, bl[3], 1.0f);
        p4 *= fmaf(ratio, bl[4], 1.0f);
    }
    p0 = warpProdF(p0); p1 = warpProdF(p1); p2 = warpProdF(p2);
    p3 = warpProdF(p3); p4 = warpProdF(p4);
    if (l == 0) {
        s_pred[w * RES + 0] = p0; s_pred[w * RES + 1] = p1;
        s_pred[w * RES + 2] = p2; s_pred[w * RES + 3] = p3;
        s_pred[w * RES + 4] = p4;
    }
    __syncthreads();
    if (t == 0) {
        float P[RES];
        #pragma unroll
        for (int j = 0; j < RES; j++) {
            float v = 1.f;
            #pragma unroll
            for (int ww = 0; ww < 4; ww++) v *= s_pred[ww * RES + j];
            P[j] = v;
        }
        const float u[RES] = {-0.5f, 0.0f, 0.5f, 1.0f, 1.5f};
        float bsum = 0.f, acc = 0.f;
        #pragma unroll
        for (int j = 0; j < RES; j++) {
            float bc = P[j] - 1.0f;
            bsum += bc;
            acc = fmaf(bc, u[j], acc);
        }
        out[b] = acc / bsum;
    }
}

extern "C" void kernel_launch(void* const* d_in, const int* in_sizes, int n_in,
                              void* d_out, int out_size) {
    const float* x = (const float*)d_in[0];
    const float* a = (const float*)d_in[1];
    const float* b = (const float*)d_in[2];
    const float* r = (const float*)d_in[3];
    const float* d = (const float*)d_in[4];
    float* out = (float*)d_out;

    prep_kernel<<<1, RULES>>>(a, b, r, d);
    main_kernel<<<BATCH, THREADS>>>(x, out);
}

// round 4
// speedup vs baseline: 1.3629x; 1.3629x over previous
#include <cuda_runtime.h>
#include <math.h>

#define RULES 512
#define FEAT  128
#define RES   5
#define BATCH 2048
#define WARPS_PER_BLOCK 16
#define THREADS (WARPS_PER_BLOCK * 32)          // 512
#define BLOCKS  (BATCH / WARPS_PER_BLOCK)       // 128  (single wave on 148 SMs)
#define RULES_PER_LANE (RULES / 32)             // 16

__device__ __forceinline__ float warpSumF(float v) {
    #pragma unroll
    for (int o = 16; o; o >>= 1) v += __shfl_xor_sync(0xffffffffu, v, o);
    return v;
}
__device__ __forceinline__ double warpSumD(double v) {
    #pragma unroll
    for (int o = 16; o; o >>= 1) v += __shfl_xor_sync(0xffffffffu, v, o);
    return v;
}

__global__ void __launch_bounds__(THREADS, 1)
fused_kernel(const float* __restrict__ x,
             const float* __restrict__ a,
             const float* __restrict__ bmat,
             const float* __restrict__ r,
             const float* __restrict__ d,
             float* __restrict__ out) {
    // Per-rule constants, computed redundantly per block (cheap, removes prep launch)
    __shared__ double sK0[RULES];               // r[i] - e^d * 128 * a[i]^2
    __shared__ double sK1[RULES];               // 2 * e^d * a[i]
    __shared__ float  sBel[RES][RULES];         // softmax(b) transposed: conflict-free LDS

    const int t = threadIdx.x;
    const int l = t & 31;
    const int w = t >> 5;

    // ---- prep: thread t handles rule t (THREADS == RULES) ----
    const float edf = expf(d[0]);               // accurate: rel-err here scales exponents ~360
    const double edd = (double)edf;
    {
        double av = (double)a[t];
        sK1[t] = 2.0 * edd * av;
        sK0[t] = (double)r[t] - edd * 128.0 * av * av;
        float bv[RES];
        float m = -1e30f;
        #pragma unroll
        for (int j = 0; j < RES; j++) { bv[j] = bmat[t * RES + j]; m = fmaxf(m, bv[j]); }
        float sum = 0.f;
        #pragma unroll
        for (int j = 0; j < RES; j++) { bv[j] = expf(bv[j] - m); sum += bv[j]; }
        float inv = 1.0f / sum;
        #pragma unroll
        for (int j = 0; j < RES; j++) sBel[j][t] = bv[j] * inv;
    }
    __syncthreads();                            // the ONLY block barrier

    // ---- one warp = one batch row ----
    const int row = blockIdx.x * WARPS_PER_BLOCK + w;

    // Sx, Sxx over 128 features (x/5), float4 per lane, butterfly leaves result in all lanes
    const float4 xv = *reinterpret_cast<const float4*>(x + row * FEAT + l * 4);
    float x0 = xv.x * 0.2f, x1 = xv.y * 0.2f, x2 = xv.z * 0.2f, x3 = xv.w * 0.2f;
    float sx  = warpSumF(x0 + x1 + x2 + x3);
    float sxx = warpSumF(fmaf(x0, x0, fmaf(x1, x1, fmaf(x2, x2, x3 * x3))));

    const double Sx    = (double)sx;
    const double edSxx = edd * (double)sxx;

    // rule activations: fp64 exponent combine, fast fp32 exp; aw stays in registers
    float aw[RULES_PER_LANE];
    double spart = 0.0;
    #pragma unroll
    for (int i = 0; i < RULES_PER_LANE; i++) {
        int rr = i * 32 + l;
        double la = fma(sK1[rr], Sx, sK0[rr]) - edSxx;
        aw[i] = __expf((float)la);
        spart += (double)aw[i];
    }
    const double s = warpSumD(spart);           // all lanes

    // evidential-reasoning combine: product over rules of (ratio*belief + 1)
    float p0 = 1.f, p1 = 1.f, p2 = 1.f, p3 = 1.f, p4 = 1.f;
    #pragma unroll
    for (int i = 0; i < RULES_PER_LANE; i++) {
        int rr = i * 32 + l;
        float den = (float)(s - (double)aw[i]); // fp64 subtraction: no cancellation blow-up
        float ratio = __fdividef(aw[i], den);
        p0 *= fmaf(ratio, sBel[0][rr], 1.0f);
        p1 *= fmaf(ratio, sBel[1][rr], 1.0f);
        p2 *= fmaf(ratio, sBel[2][rr], 1.0f);
        p3 *= fmaf(ratio, sBel[3][rr], 1.0f);
        p4 *= fmaf(ratio, sBel[4][rr], 1.0f);
    }
    // 5 independent product reductions (pipelined SHFL chains)
    #pragma unroll
    for (int o = 16; o; o >>= 1) {
        p0 *= __shfl_xor_sync(0xffffffffu, p0, o);
        p1 *= __shfl_xor_sync(0xffffffffu, p1, o);
        p2 *= __shfl_xor_sync(0xffffffffu, p2, o);
        p3 *= __shfl_xor_sync(0xffffffffu, p3, o);
        p4 *= __shfl_xor_sync(0xffffffffu, p4, o);
    }

    if (l == 0) {
        float b0 = p0 - 1.f, b1 = p1 - 1.f, b2 = p2 - 1.f, b3 = p3 - 1.f, b4 = p4 - 1.f;
        float bsum = b0 + b1 + b2 + b3 + b4;
        float acc = fmaf(b0, -0.5f, 0.f);
        acc = fmaf(b2, 0.5f, acc);
        acc = fmaf(b3, 1.0f, acc);
        acc = fmaf(b4, 1.5f, acc);
        out[row] = acc / bsum;
    }
}

extern "C" void kernel_launch(void* const* d_in, const int* in_sizes, int n_in,
                              void* d_out, int out_size) {
    const float* x = (const float*)d_in[0];
    const float* a = (const float*)d_in[1];
    const float* b = (const float*)d_in[2];
    const float* r = (const float*)d_in[3];
    const float* d = (const float*)d_in[4];
    float* out = (float*)d_out;

    fused_kernel<<<BLOCKS, THREADS>>>(x, a, b, r, d, out);
}

// round 6
// speedup vs baseline: 4.5346x; 3.3272x over previous
#include <cuda_runtime.h>
#include <math.h>

#define RULES 512
#define FEAT  128
#define RES   5
#define BATCH 2048
#define WARPS_PER_BLOCK 16
#define THREADS (WARPS_PER_BLOCK * 32)          // 512 == RULES
#define BLOCKS  (BATCH / WARPS_PER_BLOCK)       // 128  (single wave on 148 SMs)
#define RULES_PER_LANE (RULES / 32)             // 16

#define LOG2E 1.4426950408889634f

__device__ __forceinline__ float ex2f(float v) {
    float r;
    asm("ex2.approx.f32 %0, %1;" : "=f"(r) : "f"(v));
    return r;
}
__device__ __forceinline__ float warpSumF(float v) {
    #pragma unroll
    for (int o = 16; o; o >>= 1) v += __shfl_xor_sync(0xffffffffu, v, o);
    return v;
}

__global__ void __launch_bounds__(THREADS, 1)
fused_kernel(const float* __restrict__ x,
             const float* __restrict__ a,
             const float* __restrict__ bmat,
             const float* __restrict__ r,
             const float* __restrict__ d,
             float* __restrict__ out) {
    // Per-rule constants (fp32, pre-scaled by log2(e) so activation = EX2 directly)
    __shared__ float2 sK[RULES];        // (K0*log2e, K1*log2e)
    __shared__ float2 sB01[RULES];      // beliefs 0,1
    __shared__ float2 sB23[RULES];      // beliefs 2,3
    __shared__ float  sB4[RULES];       // belief  4

    const int t = threadIdx.x;
    const int l = t & 31;
    const int w = t >> 5;
    const int row = blockIdx.x * WARPS_PER_BLOCK + w;

    // Issue the global x load FIRST so DRAM latency overlaps the prep phase.
    const float4 xv = *reinterpret_cast<const float4*>(x + row * FEAT + l * 4);

    // ---- prep: thread t handles rule t (THREADS == RULES) ----
    const float ed = __expf(d[0]);
    {
        float av = a[t];
        float k1 = 2.0f * ed * av;
        float k0 = r[t] - ed * 128.0f * av * av;   // only small-|a| rules matter; fp32 fine
        sK[t] = make_float2(k0 * LOG2E, k1 * LOG2E);

        float bv[RES];
        float m = -1e30f;
        #pragma unroll
        for (int j = 0; j < RES; j++) { bv[j] = bmat[t * RES + j]; m = fmaxf(m, bv[j]); }
        float sum = 0.f;
        #pragma unroll
        for (int j = 0; j < RES; j++) { bv[j] = __expf(bv[j] - m); sum += bv[j]; }
        float inv = 1.0f / sum;
        sB01[t] = make_float2(bv[0] * inv, bv[1] * inv);
        sB23[t] = make_float2(bv[2] * inv, bv[3] * inv);
        sB4[t]  = bv[4] * inv;
    }
    __syncthreads();                    // the ONLY block barrier

    // ---- one warp = one batch row ----
    float x0 = xv.x * 0.2f, x1 = xv.y * 0.2f, x2 = xv.z * 0.2f, x3 = xv.w * 0.2f;
    float Sx  = warpSumF(x0 + x1 + x2 + x3);
    float Sxx = warpSumF(fmaf(x0, x0, fmaf(x1, x1, fmaf(x2, x2, x3 * x3))));
    const float C = ed * Sxx * LOG2E;   // common-mode term (cancels in ratios)

    // rule activations: log2-domain FFMA then raw EX2
    float aw[RULES_PER_LANE];
    float spart = 0.f;
    #pragma unroll
    for (int i = 0; i < RULES_PER_LANE; i++) {
        float2 K = sK[i * 32 + l];
        aw[i] = ex2f(fmaf(K.y, Sx, K.x) - C);   // underflows to 0 for dead rules, like ref
        spart += aw[i];
    }
    const float s = warpSumF(spart);

    // evidential-reasoning combine: product over rules of (ratio*belief + 1)
    float p0 = 1.f, p1 = 1.f, p2 = 1.f, p3 = 1.f, p4 = 1.f;
    #pragma unroll
    for (int i = 0; i < RULES_PER_LANE; i++) {
        int rr = i * 32 + l;
        float ratio = __fdividef(aw[i], s - aw[i]);
        float2 b01 = sB01[rr];
        float2 b23 = sB23[rr];
        float  b4  = sB4[rr];
        p0 *= fmaf(ratio, b01.x, 1.0f);
        p1 *= fmaf(ratio, b01.y, 1.0f);
        p2 *= fmaf(ratio, b23.x, 1.0f);
        p3 *= fmaf(ratio, b23.y, 1.0f);
        p4 *= fmaf(ratio, b4,    1.0f);
    }
    // 5 independent product reductions (pipelined SHFL chains)
    #pragma unroll
    for (int o = 16; o; o >>= 1) {
        p0 *= __shfl_xor_sync(0xffffffffu, p0, o);
        p1 *= __shfl_xor_sync(0xffffffffu, p1, o);
        p2 *= __shfl_xor_sync(0xffffffffu, p2, o);
        p3 *= __shfl_xor_sync(0xffffffffu, p3, o);
        p4 *= __shfl_xor_sync(0xffffffffu, p4, o);
    }

    if (l == 0) {
        float b0 = p0 - 1.f, b1 = p1 - 1.f, b2 = p2 - 1.f, b3 = p3 - 1.f, b4 = p4 - 1.f;
        float bsum = b0 + b1 + b2 + b3 + b4;
        float acc = fmaf(b0, -0.5f, 0.f);
        acc = fmaf(b2, 0.5f, acc);
        acc = fmaf(b3, 1.0f, acc);
        acc = fmaf(b4, 1.5f, acc);
        out[row] = acc / bsum;
    }
}

extern "C" void kernel_launch(void* const* d_in, const int* in_sizes, int n_in,
                              void* d_out, int out_size) {
    const float* x = (const float*)d_in[0];
    const float* a = (const float*)d_in[1];
    const float* b = (const float*)d_in[2];
    const float* r = (const float*)d_in[3];
    const float* d = (const float*)d_in[4];
    float* out = (float*)d_out;

    fused_kernel<<<BLOCKS, THREADS>>>(x, a, b, r, d, out);
}